// round 4
// baseline (speedup 1.0000x reference)
#include <cuda_runtime.h>
#include <math.h>

#define N_USERS 50000
#define N_ENT   100000
#define DIMS    64
#define N_REL   16
#define E_KG    1500000
#define E_IN    1000000
#define RSQRT_DK 0.17677669529663687f   /* 1/sqrt(32) */

// ---------------- static device scratch (no runtime allocation) ----------------
__device__ float g_P[N_ENT * DIMS];        // entity_emb @ W_Q
__device__ float g_ex[E_KG * 2];           // exp(score) per edge per head
__device__ float g_segsum[N_ENT * 2];      // softmax denominators
__device__ float g_ent0[N_ENT * DIMS];     // layer ping-pong buffers
__device__ float g_ent1[N_ENT * DIMS];
__device__ float g_usr0[N_USERS * DIMS];
__device__ float g_usr1[N_USERS * DIMS];
__device__ float g_ent_acc[N_ENT * DIMS];  // running sum for the mean
__device__ float g_usr_acc[N_USERS * DIMS];

// ---------------- helpers ----------------
__device__ __forceinline__ void red_add_v4(float* p, float4 v) {
    asm volatile("red.global.add.v4.f32 [%0], {%1,%2,%3,%4};"
                 :: "l"(p), "f"(v.x), "f"(v.y), "f"(v.z), "f"(v.w) : "memory");
}

// zero n4 float4's
__global__ void zero_k(float4* __restrict__ p, int n4) {
    int i = blockIdx.x * blockDim.x + threadIdx.x;
    int stride = gridDim.x * blockDim.x;
    float4 z = make_float4(0.f, 0.f, 0.f, 0.f);
    for (; i < n4; i += stride) p[i] = z;
}

// dst = src (float4 grid-stride)
__global__ void copy_k(float4* __restrict__ dst, const float4* __restrict__ src, int n4) {
    int i = blockIdx.x * blockDim.x + threadIdx.x;
    int stride = gridDim.x * blockDim.x;
    for (; i < n4; i += stride) dst[i] = src[i];
}

// acc += v
__global__ void acc_k(float4* __restrict__ acc, const float4* __restrict__ v, int n4) {
    int i = blockIdx.x * blockDim.x + threadIdx.x;
    int stride = gridDim.x * blockDim.x;
    for (; i < n4; i += stride) {
        float4 a = acc[i], b = v[i];
        a.x += b.x; a.y += b.y; a.z += b.z; a.w += b.w;
        acc[i] = a;
    }
}

// P[r,:] = X[r,:] @ W  (W is 64x64). Block: 256 threads = 16 rows x 16 col-quads.
__global__ void __launch_bounds__(256) gemm_k(const float* __restrict__ X,
                                              const float* __restrict__ W,
                                              float* __restrict__ P) {
    __shared__ float sW[64 * 64];
    __shared__ float srow[16][64];
    int tid = threadIdx.x;
    #pragma unroll
    for (int i = 0; i < 16; i++) sW[tid + i * 256] = W[tid + i * 256];
    // load 16 rows = 1024 floats = 256 float4
    const float4* X4 = (const float4*)(X + (size_t)blockIdx.x * 16 * 64);
    ((float4*)&srow[0][0])[tid] = X4[tid];
    __syncthreads();
    int r  = tid >> 4;
    int cq = (tid & 15) * 4;
    float4 acc = make_float4(0.f, 0.f, 0.f, 0.f);
    #pragma unroll
    for (int d = 0; d < 64; d++) {
        float a = srow[r][d];
        float4 b = *(const float4*)&sW[d * 64 + cq];
        acc.x += a * b.x; acc.y += a * b.y; acc.z += a * b.z; acc.w += a * b.w;
    }
    *(float4*)&P[((size_t)blockIdx.x * 16 + r) * 64 + cq] = acc;
}

// Pass A: per KG edge, score -> exp -> atomic segment sum. 16 lanes/edge.
__global__ void __launch_bounds__(256) score_k(const int* __restrict__ eidx,
                                               const int* __restrict__ etype,
                                               const float* __restrict__ relemb) {
    __shared__ float srel[N_REL * DIMS];
    int tid = threadIdx.x;
    #pragma unroll
    for (int i = 0; i < 4; i++) srel[tid + i * 256] = relemb[tid + i * 256];
    __syncthreads();
    int e  = blockIdx.x * 16 + (tid >> 4);
    int l  = tid & 15;
    int d0 = l * 4;
    int hd = eidx[e];
    int tl = eidx[E_KG + e];
    int rt = etype[e] - 1;
    float4 ph = *(const float4*)&g_P[(size_t)hd * 64 + d0];
    float4 pt = *(const float4*)&g_P[(size_t)tl * 64 + d0];
    float4 rv = *(const float4*)&srel[rt * 64 + d0];
    float part = ph.x * pt.x * rv.x + ph.y * pt.y * rv.y
               + ph.z * pt.z * rv.z + ph.w * pt.w * rv.w;
    part += __shfl_xor_sync(0xffffffffu, part, 1);
    part += __shfl_xor_sync(0xffffffffu, part, 2);
    part += __shfl_xor_sync(0xffffffffu, part, 4);
    if ((l & 7) == 0) {
        int h = l >> 3;
        float exv = __expf(part * RSQRT_DK);
        g_ex[(size_t)e * 2 + h] = exv;
        atomicAdd(&g_segsum[(size_t)hd * 2 + h], exv);
    }
}

// Pass B: msg = tail_emb * rel * attn, scatter-add into ent_new[head].
__global__ void __launch_bounds__(256) msg_k(const int* __restrict__ eidx,
                                             const int* __restrict__ etype,
                                             const float* __restrict__ relemb,
                                             const float* __restrict__ ent_cur,
                                             float* __restrict__ ent_new) {
    __shared__ float srel[N_REL * DIMS];
    int tid = threadIdx.x;
    #pragma unroll
    for (int i = 0; i < 4; i++) srel[tid + i * 256] = relemb[tid + i * 256];
    __syncthreads();
    int e  = blockIdx.x * 16 + (tid >> 4);
    int l  = tid & 15;
    int d0 = l * 4;
    int h  = l >> 3;
    int hd = eidx[e];
    int tl = eidx[E_KG + e];
    int rt = etype[e] - 1;
    float attn = g_ex[(size_t)e * 2 + h] / g_segsum[(size_t)hd * 2 + h];
    float4 te = *(const float4*)&ent_cur[(size_t)tl * 64 + d0];
    float4 rv = *(const float4*)&srel[rt * 64 + d0];
    float4 m;
    m.x = te.x * rv.x * attn; m.y = te.y * rv.y * attn;
    m.z = te.z * rv.z * attn; m.w = te.w * rv.w * attn;
    red_add_v4(&ent_new[(size_t)hd * 64 + d0], m);
}

// Row-wise L2 normalize (one warp per row).
__global__ void __launch_bounds__(256) norm_k(float* __restrict__ x) {
    int row  = blockIdx.x * 8 + (threadIdx.x >> 5);
    int lane = threadIdx.x & 31;
    float2 v = *(float2*)&x[(size_t)row * 64 + lane * 2];
    float s = v.x * v.x + v.y * v.y;
    #pragma unroll
    for (int o = 16; o; o >>= 1) s += __shfl_xor_sync(0xffffffffu, s, o);
    float inv = 1.0f / fmaxf(sqrtf(s), 1e-12f);
    v.x *= inv; v.y *= inv;
    *(float2*)&x[(size_t)row * 64 + lane * 2] = v;
}

// Bipartite pass: usr_new[u] += w*ent_cur[it];  ent_new[it] += w*usr_cur[u].
__global__ void __launch_bounds__(256) inter_k(const int* __restrict__ iedge,
                                               const float* __restrict__ iw,
                                               const float* __restrict__ ent_cur,
                                               const float* __restrict__ usr_cur,
                                               float* __restrict__ ent_new,
                                               float* __restrict__ usr_new) {
    int e  = blockIdx.x * 16 + (threadIdx.x >> 4);
    int l  = threadIdx.x & 15;
    int d0 = l * 4;
    int u  = iedge[e];
    int it = iedge[E_IN + e];
    float w = iw[e];
    float4 ev = *(const float4*)&ent_cur[(size_t)it * 64 + d0];
    float4 a; a.x = w * ev.x; a.y = w * ev.y; a.z = w * ev.z; a.w = w * ev.w;
    red_add_v4(&usr_new[(size_t)u * 64 + d0], a);
    float4 uv = *(const float4*)&usr_cur[(size_t)u * 64 + d0];
    float4 b; b.x = w * uv.x; b.y = w * uv.y; b.z = w * uv.z; b.w = w * uv.w;
    red_add_v4(&ent_new[(size_t)it * 64 + d0], b);
}

// out = [usr_acc/3 ; ent_acc/3]
__global__ void final_k(const float4* __restrict__ usr_acc,
                        const float4* __restrict__ ent_acc,
                        float4* __restrict__ out) {
    const int NU4 = N_USERS * DIMS / 4;
    const int NT4 = NU4 + N_ENT * DIMS / 4;
    const float c = 1.0f / 3.0f;
    int i = blockIdx.x * blockDim.x + threadIdx.x;
    int stride = gridDim.x * blockDim.x;
    for (; i < NT4; i += stride) {
        float4 v = (i < NU4) ? usr_acc[i] : ent_acc[i - NU4];
        v.x *= c; v.y *= c; v.z *= c; v.w *= c;
        out[i] = v;
    }
}

// ---------------- launcher ----------------
extern "C" void kernel_launch(void* const* d_in, const int* in_sizes, int n_in,
                              void* d_out, int out_size) {
    const float* user_emb   = (const float*)d_in[1];
    const float* entity_emb = (const float*)d_in[2];
    const int*   inter_edge = (const int*)d_in[3];
    const float* inter_w    = (const float*)d_in[4];
    const int*   edge_index = (const int*)d_in[5];
    const int*   edge_type  = (const int*)d_in[6];
    const float* rel_emb    = (const float*)d_in[7];
    const float* W_Q        = (const float*)d_in[8];
    float* out = (float*)d_out;

    float *p_P, *p_segsum, *p_ent0, *p_ent1, *p_usr0, *p_usr1, *p_eacc, *p_uacc;
    cudaGetSymbolAddress((void**)&p_P,      g_P);
    cudaGetSymbolAddress((void**)&p_segsum, g_segsum);
    cudaGetSymbolAddress((void**)&p_ent0,   g_ent0);
    cudaGetSymbolAddress((void**)&p_ent1,   g_ent1);
    cudaGetSymbolAddress((void**)&p_usr0,   g_usr0);
    cudaGetSymbolAddress((void**)&p_usr1,   g_usr1);
    cudaGetSymbolAddress((void**)&p_eacc,   g_ent_acc);
    cudaGetSymbolAddress((void**)&p_uacc,   g_usr_acc);

    const int TB = 256;
    const int ENT4 = N_ENT * DIMS / 4;     // 1,600,000
    const int USR4 = N_USERS * DIMS / 4;   //   800,000
    const int CP_BLOCKS = 1024;

    // acc starts at the layer-0 embeddings
    copy_k<<<CP_BLOCKS, TB>>>((float4*)p_eacc, (const float4*)entity_emb, ENT4);
    copy_k<<<CP_BLOCKS, TB>>>((float4*)p_uacc, (const float4*)user_emb,   USR4);

    // hardcoded layers_num = 2 (graph must be statically shaped)
    for (int L = 0; L < 2; L++) {
        const float* ecur = (L == 0) ? entity_emb : p_ent0;
        const float* ucur = (L == 0) ? user_emb   : p_usr0;
        float* enew = (L == 0) ? p_ent0 : p_ent1;
        float* unew = (L == 0) ? p_usr0 : p_usr1;

        zero_k<<<256, TB>>>((float4*)p_segsum, N_ENT * 2 / 4);
        zero_k<<<CP_BLOCKS, TB>>>((float4*)enew, ENT4);
        zero_k<<<CP_BLOCKS, TB>>>((float4*)unew, USR4);

        gemm_k<<<N_ENT / 16, TB>>>(ecur, W_Q, p_P);
        score_k<<<E_KG / 16, TB>>>(edge_index, edge_type, rel_emb);
        msg_k<<<E_KG / 16, TB>>>(edge_index, edge_type, rel_emb, ecur, enew);
        norm_k<<<N_ENT / 8, TB>>>(enew);
        inter_k<<<E_IN / 16, TB>>>(inter_edge, inter_w, ecur, ucur, enew, unew);

        acc_k<<<CP_BLOCKS, TB>>>((float4*)p_eacc, (const float4*)enew, ENT4);
        acc_k<<<CP_BLOCKS, TB>>>((float4*)p_uacc, (const float4*)unew, USR4);
    }

    final_k<<<2048, TB>>>((const float4*)p_uacc, (const float4*)p_eacc, (float4*)out);
}

// round 5
// speedup vs baseline: 1.3235x; 1.3235x over previous
#include <cuda_runtime.h>
#include <math.h>

#define N_USERS 50000
#define N_ENT   100000
#define DIMS    64
#define N_REL   16
#define E_KG    1500000
#define E_IN    1000000
#define RSQRT_DK 0.17677669529663687f   /* 1/sqrt(32) */

// ---------------- static device scratch (no runtime allocation) ----------------
__device__ float g_P[N_ENT * DIMS];        // entity_emb @ W_Q
__device__ float g_segsum[N_ENT * 2];      // softmax denominators (per head)
__device__ float g_ent0[N_ENT * DIMS];     // layer buffers (kept for final mean)
__device__ float g_ent1[N_ENT * DIMS];
__device__ float g_usr0[N_USERS * DIMS];
__device__ float g_usr1[N_USERS * DIMS];

// ---------------- helpers ----------------
__device__ __forceinline__ void red_add_v4(float* p, float4 v) {
    asm volatile("red.global.add.v4.f32 [%0], {%1,%2,%3,%4};"
                 :: "l"(p), "f"(v.x), "f"(v.y), "f"(v.z), "f"(v.w) : "memory");
}

// Zero three buffers in one launch (grid-stride over the union).
__global__ void zero3_k(float4* __restrict__ a, int na,
                        float4* __restrict__ b, int nb,
                        float4* __restrict__ c, int nc) {
    int i = blockIdx.x * blockDim.x + threadIdx.x;
    int stride = gridDim.x * blockDim.x;
    int nab = na + nb, tot = nab + nc;
    float4 z = make_float4(0.f, 0.f, 0.f, 0.f);
    for (; i < tot; i += stride) {
        if (i < na) a[i] = z;
        else if (i < nab) b[i - na] = z;
        else c[i - nab] = z;
    }
}

// P[r,:] = X[r,:] @ W  (W is 64x64). Block: 256 threads = 16 rows x 16 col-quads.
__global__ void __launch_bounds__(256) gemm_k(const float* __restrict__ X,
                                              const float* __restrict__ W,
                                              float* __restrict__ P) {
    __shared__ float sW[64 * 64];
    __shared__ float srow[16][64];
    int tid = threadIdx.x;
    #pragma unroll
    for (int i = 0; i < 16; i++) sW[tid + i * 256] = W[tid + i * 256];
    const float4* X4 = (const float4*)(X + (size_t)blockIdx.x * 16 * 64);
    ((float4*)&srow[0][0])[tid] = X4[tid];
    __syncthreads();
    int r  = tid >> 4;
    int cq = (tid & 15) * 4;
    float4 acc = make_float4(0.f, 0.f, 0.f, 0.f);
    #pragma unroll
    for (int d = 0; d < 64; d++) {
        float a = srow[r][d];
        float4 b = *(const float4*)&sW[d * 64 + cq];
        acc.x += a * b.x; acc.y += a * b.y; acc.z += a * b.z; acc.w += a * b.w;
    }
    *(float4*)&P[((size_t)blockIdx.x * 16 + r) * 64 + cq] = acc;
}

// Fused edge pass: score -> exp -> scatter ex*value into ent_new and ex into segsum.
// 16 lanes per edge, one float4 per lane. Heads = 8-lane halves.
__global__ void __launch_bounds__(256) edge_k(const int* __restrict__ eidx,
                                              const int* __restrict__ etype,
                                              const float* __restrict__ relemb,
                                              const float* __restrict__ P,
                                              const float* __restrict__ ent_cur,
                                              float* __restrict__ ent_new,
                                              float* __restrict__ segsum) {
    __shared__ float srel[N_REL * DIMS];
    int tid = threadIdx.x;
    #pragma unroll
    for (int i = 0; i < 4; i++) srel[tid + i * 256] = relemb[tid + i * 256];
    __syncthreads();
    int e  = blockIdx.x * 16 + (tid >> 4);
    int l  = tid & 15;
    int d0 = l * 4;
    int hd = eidx[e];
    int tl = eidx[E_KG + e];
    int rt = etype[e] - 1;
    float4 ph = *(const float4*)&P[(size_t)hd * 64 + d0];
    float4 pt = *(const float4*)&P[(size_t)tl * 64 + d0];
    float4 rv = *(const float4*)&srel[rt * 64 + d0];
    float part = ph.x * pt.x * rv.x + ph.y * pt.y * rv.y
               + ph.z * pt.z * rv.z + ph.w * pt.w * rv.w;
    // sum within each 8-lane half (one head per half); every lane ends with its head's score
    part += __shfl_xor_sync(0xffffffffu, part, 1);
    part += __shfl_xor_sync(0xffffffffu, part, 2);
    part += __shfl_xor_sync(0xffffffffu, part, 4);
    float ex = __expf(part * RSQRT_DK);
    if ((l & 7) == 0)
        atomicAdd(&segsum[(size_t)hd * 2 + (l >> 3)], ex);
    float4 te = *(const float4*)&ent_cur[(size_t)tl * 64 + d0];
    float4 m;
    m.x = te.x * rv.x * ex; m.y = te.y * rv.y * ex;
    m.z = te.z * rv.z * ex; m.w = te.w * rv.w * ex;
    red_add_v4(&ent_new[(size_t)hd * 64 + d0], m);
}

// Per-row: divide each head-half by its softmax denominator, then L2 normalize.
// One warp per row; lanes 0-15 -> dims 0-31 (head 0), lanes 16-31 -> head 1.
__global__ void __launch_bounds__(256) norm_k(float* __restrict__ x,
                                              const float* __restrict__ segsum) {
    int row  = blockIdx.x * 8 + (threadIdx.x >> 5);
    int lane = threadIdx.x & 31;
    float ss = segsum[(size_t)row * 2 + (lane >> 4)];
    float invs = (ss != 0.f) ? (1.f / ss) : 1.f;
    float2 v = *(float2*)&x[(size_t)row * 64 + lane * 2];
    v.x *= invs; v.y *= invs;
    float s = v.x * v.x + v.y * v.y;
    #pragma unroll
    for (int o = 16; o; o >>= 1) s += __shfl_xor_sync(0xffffffffu, s, o);
    float inv = 1.0f / fmaxf(sqrtf(s), 1e-12f);
    v.x *= inv; v.y *= inv;
    *(float2*)&x[(size_t)row * 64 + lane * 2] = v;
}

// Bipartite pass: usr_new[u] += w*ent_cur[it];  ent_new[it] += w*usr_cur[u].
__global__ void __launch_bounds__(256) inter_k(const int* __restrict__ iedge,
                                               const float* __restrict__ iw,
                                               const float* __restrict__ ent_cur,
                                               const float* __restrict__ usr_cur,
                                               float* __restrict__ ent_new,
                                               float* __restrict__ usr_new) {
    int e  = blockIdx.x * 16 + (threadIdx.x >> 4);
    int l  = threadIdx.x & 15;
    int d0 = l * 4;
    int u  = iedge[e];
    int it = iedge[E_IN + e];
    float w = iw[e];
    float4 ev = *(const float4*)&ent_cur[(size_t)it * 64 + d0];
    float4 a; a.x = w * ev.x; a.y = w * ev.y; a.z = w * ev.z; a.w = w * ev.w;
    red_add_v4(&usr_new[(size_t)u * 64 + d0], a);
    float4 uv = *(const float4*)&usr_cur[(size_t)u * 64 + d0];
    float4 b; b.x = w * uv.x; b.y = w * uv.y; b.z = w * uv.z; b.w = w * uv.w;
    red_add_v4(&ent_new[(size_t)it * 64 + d0], b);
}

// out = [ (u0+u1+u2)/3 ; (e0+e1+e2)/3 ]
__global__ void final_k(const float4* __restrict__ u0, const float4* __restrict__ u1,
                        const float4* __restrict__ u2,
                        const float4* __restrict__ e0, const float4* __restrict__ e1,
                        const float4* __restrict__ e2,
                        float4* __restrict__ out) {
    const int NU4 = N_USERS * DIMS / 4;
    const int NT4 = NU4 + N_ENT * DIMS / 4;
    const float c = 1.0f / 3.0f;
    int i = blockIdx.x * blockDim.x + threadIdx.x;
    int stride = gridDim.x * blockDim.x;
    for (; i < NT4; i += stride) {
        float4 a, b, d;
        if (i < NU4) { a = u0[i]; b = u1[i]; d = u2[i]; }
        else { int j = i - NU4; a = e0[j]; b = e1[j]; d = e2[j]; }
        float4 v;
        v.x = (a.x + b.x + d.x) * c;
        v.y = (a.y + b.y + d.y) * c;
        v.z = (a.z + b.z + d.z) * c;
        v.w = (a.w + b.w + d.w) * c;
        out[i] = v;
    }
}

// ---------------- launcher ----------------
extern "C" void kernel_launch(void* const* d_in, const int* in_sizes, int n_in,
                              void* d_out, int out_size) {
    const float* user_emb   = (const float*)d_in[1];
    const float* entity_emb = (const float*)d_in[2];
    const int*   inter_edge = (const int*)d_in[3];
    const float* inter_w    = (const float*)d_in[4];
    const int*   edge_index = (const int*)d_in[5];
    const int*   edge_type  = (const int*)d_in[6];
    const float* rel_emb    = (const float*)d_in[7];
    const float* W_Q        = (const float*)d_in[8];
    float* out = (float*)d_out;

    float *p_P, *p_segsum, *p_ent0, *p_ent1, *p_usr0, *p_usr1;
    cudaGetSymbolAddress((void**)&p_P,      g_P);
    cudaGetSymbolAddress((void**)&p_segsum, g_segsum);
    cudaGetSymbolAddress((void**)&p_ent0,   g_ent0);
    cudaGetSymbolAddress((void**)&p_ent1,   g_ent1);
    cudaGetSymbolAddress((void**)&p_usr0,   g_usr0);
    cudaGetSymbolAddress((void**)&p_usr1,   g_usr1);

    const int TB = 256;
    const int ENT4 = N_ENT * DIMS / 4;     // 1,600,000
    const int USR4 = N_USERS * DIMS / 4;   //   800,000
    const int SEG4 = N_ENT * 2 / 4;        //      50,000

    // hardcoded layers_num = 2 (graph must be statically shaped)
    for (int L = 0; L < 2; L++) {
        const float* ecur = (L == 0) ? entity_emb : p_ent0;
        const float* ucur = (L == 0) ? user_emb   : p_usr0;
        float* enew = (L == 0) ? p_ent0 : p_ent1;
        float* unew = (L == 0) ? p_usr0 : p_usr1;

        zero3_k<<<1536, TB>>>((float4*)enew, ENT4, (float4*)unew, USR4,
                              (float4*)p_segsum, SEG4);
        gemm_k<<<N_ENT / 16, TB>>>(ecur, W_Q, p_P);
        edge_k<<<E_KG / 16, TB>>>(edge_index, edge_type, rel_emb, p_P, ecur,
                                  enew, p_segsum);
        norm_k<<<N_ENT / 8, TB>>>(enew, p_segsum);
        inter_k<<<E_IN / 16, TB>>>(inter_edge, inter_w, ecur, ucur, enew, unew);
    }

    final_k<<<2048, TB>>>((const float4*)user_emb, (const float4*)p_usr0,
                          (const float4*)p_usr1,
                          (const float4*)entity_emb, (const float4*)p_ent0,
                          (const float4*)p_ent1, (float4*)out);
}

// round 6
// speedup vs baseline: 1.4990x; 1.1326x over previous
#include <cuda_runtime.h>
#include <cuda_bf16.h>
#include <math.h>

#define N_USERS 50000
#define N_ENT   100000
#define DIMS    64
#define N_REL   16
#define E_KG    1500000
#define E_IN    1000000
#define RSQRT_DK 0.17677669529663687f   /* 1/sqrt(32) */

// ---------------- static device scratch (no runtime allocation) ----------------
__device__ __nv_bfloat162 g_P[N_ENT * 32];   // entity_emb @ W_Q, bf16 (scores only)
__device__ float g_ent0[N_ENT * DIMS];       // layer buffers (kept for final mean)
__device__ float g_ent1[N_ENT * DIMS];
__device__ float g_usr0[N_USERS * DIMS];
__device__ float g_usr1[N_USERS * DIMS];

// CSR structures (built once per call)
__device__ int g_kg_row[N_ENT + 1];
__device__ int g_kg_cur[N_ENT];              // counter, then cursor
__device__ unsigned g_kg_pk[E_KG];           // tail | (rel<<20)
__device__ int g_iu_row[N_USERS + 1];
__device__ int g_iu_cur[N_USERS];
__device__ int2 g_iu_pk[E_IN];               // {item, w bits}
__device__ int g_ii_row[N_ENT + 1];
__device__ int g_ii_cur[N_ENT];
__device__ int2 g_ii_pk[E_IN];               // {user, w bits}

// ---------------- CSR build ----------------
__global__ void zero_cnt_k(int* __restrict__ a, int na, int* __restrict__ b, int nb,
                           int* __restrict__ c, int nc) {
    int i = blockIdx.x * blockDim.x + threadIdx.x;
    int stride = gridDim.x * blockDim.x;
    int nab = na + nb, tot = nab + nc;
    for (; i < tot; i += stride) {
        if (i < na) a[i] = 0;
        else if (i < nab) b[i - na] = 0;
        else c[i - nab] = 0;
    }
}

__global__ void hist_k(const int* __restrict__ eidx, const int* __restrict__ iedge,
                       int* __restrict__ kg_cnt, int* __restrict__ iu_cnt,
                       int* __restrict__ ii_cnt) {
    int stride = gridDim.x * blockDim.x;
    for (int i = blockIdx.x * blockDim.x + threadIdx.x; i < E_KG; i += stride)
        atomicAdd(&kg_cnt[eidx[i]], 1);
    for (int i = blockIdx.x * blockDim.x + threadIdx.x; i < E_IN; i += stride) {
        atomicAdd(&iu_cnt[iedge[i]], 1);
        atomicAdd(&ii_cnt[iedge[E_IN + i]], 1);
    }
}

// One-block exclusive scan (n multiple of 4). Writes row[0..n] and cursor copy.
// cnt may alias cur (each element read by the same thread before being written).
__global__ void __launch_bounds__(1024) scan_k(const int* __restrict__ cnt, int n,
                                               int* __restrict__ row,
                                               int* __restrict__ cur) {
    __shared__ int wsum[32];
    __shared__ int base_s;
    int tid = threadIdx.x;
    int lane = tid & 31, w = tid >> 5;
    if (tid == 0) base_s = 0;
    __syncthreads();
    for (int b = 0; b < n; b += 4096) {
        int i = b + tid * 4;
        int4 v = (i + 3 < n) ? *(const int4*)&cnt[i] : make_int4(0, 0, 0, 0);
        int tsum = v.x + v.y + v.z + v.w;
        int x = tsum;
        #pragma unroll
        for (int o = 1; o < 32; o <<= 1) {
            int y = __shfl_up_sync(0xffffffffu, x, o);
            if (lane >= o) x += y;
        }
        if (lane == 31) wsum[w] = x;
        __syncthreads();
        if (w == 0) {
            int s = wsum[lane];
            #pragma unroll
            for (int o = 1; o < 32; o <<= 1) {
                int y = __shfl_up_sync(0xffffffffu, s, o);
                if (lane >= o) s += y;
            }
            wsum[lane] = s;
        }
        __syncthreads();
        int excl = x - tsum + (w ? wsum[w - 1] : 0) + base_s;
        if (i + 3 < n) {
            int4 out = make_int4(excl, excl + v.x, excl + v.x + v.y,
                                 excl + v.x + v.y + v.z);
            *(int4*)&row[i] = out;
            *(int4*)&cur[i] = out;
        }
        __syncthreads();
        if (tid == 1023) base_s = excl + tsum;
        __syncthreads();
    }
    if (tid == 0) row[n] = base_s;
}

__global__ void scatter_k(const int* __restrict__ eidx, const int* __restrict__ etype,
                          const int* __restrict__ iedge, const float* __restrict__ iw,
                          int* __restrict__ kg_cur, unsigned* __restrict__ kg_pk,
                          int* __restrict__ iu_cur, int2* __restrict__ iu_pk,
                          int* __restrict__ ii_cur, int2* __restrict__ ii_pk) {
    int stride = gridDim.x * blockDim.x;
    for (int i = blockIdx.x * blockDim.x + threadIdx.x; i < E_KG; i += stride) {
        int hd = eidx[i];
        unsigned tl = (unsigned)eidx[E_KG + i];
        unsigned rt = (unsigned)(etype[i] - 1);
        int pos = atomicAdd(&kg_cur[hd], 1);
        kg_pk[pos] = tl | (rt << 20);
    }
    for (int i = blockIdx.x * blockDim.x + threadIdx.x; i < E_IN; i += stride) {
        int u = iedge[i];
        int it = iedge[E_IN + i];
        int wb = __float_as_int(iw[i]);
        int p1 = atomicAdd(&iu_cur[u], 1);
        iu_pk[p1] = make_int2(it, wb);
        int p2 = atomicAdd(&ii_cur[it], 1);
        ii_pk[p2] = make_int2(u, wb);
    }
}

// ---------------- per-layer kernels ----------------
// P[r,:] = X[r,:] @ W (64x64), output bf16. 256 threads = 16 rows x 16 col-quads.
__global__ void __launch_bounds__(256) gemm_k(const float* __restrict__ X,
                                              const float* __restrict__ W,
                                              __nv_bfloat162* __restrict__ P) {
    __shared__ float sW[64 * 64];
    __shared__ float srow[16][64];
    int tid = threadIdx.x;
    #pragma unroll
    for (int i = 0; i < 16; i++) sW[tid + i * 256] = W[tid + i * 256];
    const float4* X4 = (const float4*)(X + (size_t)blockIdx.x * 16 * 64);
    ((float4*)&srow[0][0])[tid] = X4[tid];
    __syncthreads();
    int r  = tid >> 4;
    int cq = (tid & 15) * 4;
    float4 acc = make_float4(0.f, 0.f, 0.f, 0.f);
    #pragma unroll
    for (int d = 0; d < 64; d++) {
        float a = srow[r][d];
        float4 b = *(const float4*)&sW[d * 64 + cq];
        acc.x += a * b.x; acc.y += a * b.y; acc.z += a * b.z; acc.w += a * b.w;
    }
    size_t o = ((size_t)blockIdx.x * 16 + r) * 32 + (cq >> 1);
    P[o]     = __float22bfloat162_rn(make_float2(acc.x, acc.y));
    P[o + 1] = __float22bfloat162_rn(make_float2(acc.z, acc.w));
}

// Fused entity update: one warp per entity.
// KG attention aggregation (softmax folded into final divide) -> L2 normalize
// -> add user-side aggregation -> single write. Lane l owns dims 2l, 2l+1.
__global__ void __launch_bounds__(256) ent_k(const int* __restrict__ kg_row,
                                             const unsigned* __restrict__ kg_pk,
                                             const int* __restrict__ ii_row,
                                             const int2* __restrict__ ii_pk,
                                             const __nv_bfloat162* __restrict__ P,
                                             const float* __restrict__ ent_cur,
                                             const float* __restrict__ usr_cur,
                                             const float* __restrict__ relemb,
                                             float* __restrict__ ent_new) {
    __shared__ float srel[N_REL * DIMS];
    int tid = threadIdx.x;
    #pragma unroll
    for (int i = 0; i < 4; i++) srel[tid + i * 256] = relemb[tid + i * 256];
    __syncthreads();

    int row  = blockIdx.x * 8 + (tid >> 5);
    int lane = tid & 31;
    int d0   = lane * 2;

    float2 ph = __bfloat1622float2(P[(size_t)row * 32 + lane]);

    float2 acc = make_float2(0.f, 0.f);
    float ssum = 0.f;
    int s = kg_row[row], e = kg_row[row + 1];
    for (int j = s; j < e; j++) {
        unsigned pk = kg_pk[j];
        int tl = (int)(pk & 0xFFFFFu);
        int rt = (int)(pk >> 20);
        float2 pt = __bfloat1622float2(P[(size_t)tl * 32 + lane]);
        float2 rv = *(const float2*)&srel[rt * 64 + d0];
        float2 te = *(const float2*)&ent_cur[(size_t)tl * 64 + d0];
        float part = ph.x * pt.x * rv.x + ph.y * pt.y * rv.y;
        // reduce within each 16-lane half (head 0 = lanes 0-15, head 1 = 16-31)
        part += __shfl_xor_sync(0xffffffffu, part, 1);
        part += __shfl_xor_sync(0xffffffffu, part, 2);
        part += __shfl_xor_sync(0xffffffffu, part, 4);
        part += __shfl_xor_sync(0xffffffffu, part, 8);
        float ex = __expf(part * RSQRT_DK);
        ssum += ex;
        acc.x += ex * te.x * rv.x;
        acc.y += ex * te.y * rv.y;
    }
    float invs = (ssum > 0.f) ? (1.f / ssum) : 1.f;
    acc.x *= invs; acc.y *= invs;

    // L2 normalize over all 64 dims
    float s2 = acc.x * acc.x + acc.y * acc.y;
    #pragma unroll
    for (int o = 16; o; o >>= 1) s2 += __shfl_xor_sync(0xffffffffu, s2, o);
    float invn = 1.0f / fmaxf(sqrtf(s2), 1e-12f);
    acc.x *= invn; acc.y *= invn;

    // user -> entity aggregation
    int s2i = ii_row[row], e2i = ii_row[row + 1];
    for (int j = s2i; j < e2i; j++) {
        int2 p = ii_pk[j];
        float w = __int_as_float(p.y);
        float2 uv = *(const float2*)&usr_cur[(size_t)p.x * 64 + d0];
        acc.x += w * uv.x;
        acc.y += w * uv.y;
    }
    *(float2*)&ent_new[(size_t)row * 64 + d0] = acc;
}

// User update: one warp per user. usr_new[u] = sum w * ent_cur[item].
__global__ void __launch_bounds__(256) usr_k(const int* __restrict__ iu_row,
                                             const int2* __restrict__ iu_pk,
                                             const float* __restrict__ ent_cur,
                                             float* __restrict__ usr_new) {
    int tid  = threadIdx.x;
    int row  = blockIdx.x * 8 + (tid >> 5);
    int lane = tid & 31;
    int d0   = lane * 2;
    float2 acc = make_float2(0.f, 0.f);
    int s = iu_row[row], e = iu_row[row + 1];
    for (int j = s; j < e; j++) {
        int2 p = iu_pk[j];
        float w = __int_as_float(p.y);
        float2 ev = *(const float2*)&ent_cur[(size_t)p.x * 64 + d0];
        acc.x += w * ev.x;
        acc.y += w * ev.y;
    }
    *(float2*)&usr_new[(size_t)row * 64 + d0] = acc;
}

// out = [ (u0+u1+u2)/3 ; (e0+e1+e2)/3 ]
__global__ void final_k(const float4* __restrict__ u0, const float4* __restrict__ u1,
                        const float4* __restrict__ u2,
                        const float4* __restrict__ e0, const float4* __restrict__ e1,
                        const float4* __restrict__ e2,
                        float4* __restrict__ out) {
    const int NU4 = N_USERS * DIMS / 4;
    const int NT4 = NU4 + N_ENT * DIMS / 4;
    const float c = 1.0f / 3.0f;
    int i = blockIdx.x * blockDim.x + threadIdx.x;
    int stride = gridDim.x * blockDim.x;
    for (; i < NT4; i += stride) {
        float4 a, b, d;
        if (i < NU4) { a = u0[i]; b = u1[i]; d = u2[i]; }
        else { int j = i - NU4; a = e0[j]; b = e1[j]; d = e2[j]; }
        float4 v;
        v.x = (a.x + b.x + d.x) * c;
        v.y = (a.y + b.y + d.y) * c;
        v.z = (a.z + b.z + d.z) * c;
        v.w = (a.w + b.w + d.w) * c;
        out[i] = v;
    }
}

// ---------------- launcher ----------------
extern "C" void kernel_launch(void* const* d_in, const int* in_sizes, int n_in,
                              void* d_out, int out_size) {
    const float* user_emb   = (const float*)d_in[1];
    const float* entity_emb = (const float*)d_in[2];
    const int*   inter_edge = (const int*)d_in[3];
    const float* inter_w    = (const float*)d_in[4];
    const int*   edge_index = (const int*)d_in[5];
    const int*   edge_type  = (const int*)d_in[6];
    const float* rel_emb    = (const float*)d_in[7];
    const float* W_Q        = (const float*)d_in[8];
    float* out = (float*)d_out;

    __nv_bfloat162* p_P;
    float *p_ent0, *p_ent1, *p_usr0, *p_usr1;
    int *p_kg_row, *p_kg_cur, *p_iu_row, *p_iu_cur, *p_ii_row, *p_ii_cur;
    unsigned* p_kg_pk;
    int2 *p_iu_pk, *p_ii_pk;
    cudaGetSymbolAddress((void**)&p_P,      g_P);
    cudaGetSymbolAddress((void**)&p_ent0,   g_ent0);
    cudaGetSymbolAddress((void**)&p_ent1,   g_ent1);
    cudaGetSymbolAddress((void**)&p_usr0,   g_usr0);
    cudaGetSymbolAddress((void**)&p_usr1,   g_usr1);
    cudaGetSymbolAddress((void**)&p_kg_row, g_kg_row);
    cudaGetSymbolAddress((void**)&p_kg_cur, g_kg_cur);
    cudaGetSymbolAddress((void**)&p_kg_pk,  g_kg_pk);
    cudaGetSymbolAddress((void**)&p_iu_row, g_iu_row);
    cudaGetSymbolAddress((void**)&p_iu_cur, g_iu_cur);
    cudaGetSymbolAddress((void**)&p_iu_pk,  g_iu_pk);
    cudaGetSymbolAddress((void**)&p_ii_row, g_ii_row);
    cudaGetSymbolAddress((void**)&p_ii_cur, g_ii_cur);
    cudaGetSymbolAddress((void**)&p_ii_pk,  g_ii_pk);

    const int TB = 256;

    // ---- CSR build (shared by both layers) ----
    zero_cnt_k<<<512, TB>>>(p_kg_cur, N_ENT, p_iu_cur, N_USERS, p_ii_cur, N_ENT);
    hist_k<<<4096, TB>>>(edge_index, inter_edge, p_kg_cur, p_iu_cur, p_ii_cur);
    scan_k<<<1, 1024>>>(p_kg_cur, N_ENT,   p_kg_row, p_kg_cur);
    scan_k<<<1, 1024>>>(p_iu_cur, N_USERS, p_iu_row, p_iu_cur);
    scan_k<<<1, 1024>>>(p_ii_cur, N_ENT,   p_ii_row, p_ii_cur);
    scatter_k<<<4096, TB>>>(edge_index, edge_type, inter_edge, inter_w,
                            p_kg_cur, p_kg_pk, p_iu_cur, p_iu_pk, p_ii_cur, p_ii_pk);

    // ---- hardcoded layers_num = 2 ----
    for (int L = 0; L < 2; L++) {
        const float* ecur = (L == 0) ? entity_emb : p_ent0;
        const float* ucur = (L == 0) ? user_emb   : p_usr0;
        float* enew = (L == 0) ? p_ent0 : p_ent1;
        float* unew = (L == 0) ? p_usr0 : p_usr1;

        gemm_k<<<N_ENT / 16, TB>>>(ecur, W_Q, p_P);
        ent_k<<<N_ENT / 8, TB>>>(p_kg_row, p_kg_pk, p_ii_row, p_ii_pk,
                                 p_P, ecur, ucur, rel_emb, enew);
        usr_k<<<N_USERS / 8, TB>>>(p_iu_row, p_iu_pk, ecur, unew);
    }

    final_k<<<2048, TB>>>((const float4*)user_emb, (const float4*)p_usr0,
                          (const float4*)p_usr1,
                          (const float4*)entity_emb, (const float4*)p_ent0,
                          (const float4*)p_ent1, (float4*)out);
}

// round 8
// speedup vs baseline: 1.7390x; 1.1601x over previous
#include <cuda_runtime.h>
#include <cuda_bf16.h>
#include <math.h>

#define N_USERS 50000
#define N_ENT   100000
#define DIMS    64
#define N_REL   16
#define E_KG    1500000
#define E_IN    1000000
#define RSQRT_DK 0.17677669529663687f   /* 1/sqrt(32) */

#define NB_ENT (N_ENT / 8)     /* 12500 entity blocks (8 warps = 8 rows each) */
#define NB_USR (N_USERS / 8)   /*  6250 user blocks */

// ---------------- static device scratch (no runtime allocation) ----------------
__device__ __nv_bfloat162 g_P[N_ENT * 32];   // entity_emb @ W_Q, bf16 (scores only)
__device__ float g_ent0[N_ENT * DIMS];       // layer-1 entity output
__device__ float g_usr0[N_USERS * DIMS];     // layer-1 user output

// CSR structures (built once per call)
__device__ int g_kg_row[N_ENT + 1];
__device__ int g_kg_cur[N_ENT];              // counter, then cursor
__device__ unsigned g_kg_pk[E_KG];           // tail | (rel<<20)
__device__ int g_iu_row[N_USERS + 1];
__device__ int g_iu_cur[N_USERS];
__device__ int2 g_iu_pk[E_IN];               // {item, w bits}
__device__ int g_ii_row[N_ENT + 1];
__device__ int g_ii_cur[N_ENT];
__device__ int2 g_ii_pk[E_IN];               // {user, w bits}

// ---------------- helpers ----------------
// Reduce within each 16-lane half of the warp (butterfly). Every lane ends
// with the sum over its half.
__device__ __forceinline__ float half_reduce(float v) {
    v += __shfl_xor_sync(0xffffffffu, v, 1);
    v += __shfl_xor_sync(0xffffffffu, v, 2);
    v += __shfl_xor_sync(0xffffffffu, v, 4);
    v += __shfl_xor_sync(0xffffffffu, v, 8);
    return v;
}

// ---------------- CSR build ----------------
__global__ void zero_cnt_k(int* __restrict__ a, int na, int* __restrict__ b, int nb,
                           int* __restrict__ c, int nc) {
    int i = blockIdx.x * blockDim.x + threadIdx.x;
    int stride = gridDim.x * blockDim.x;
    int nab = na + nb, tot = nab + nc;
    for (; i < tot; i += stride) {
        if (i < na) a[i] = 0;
        else if (i < nab) b[i - na] = 0;
        else c[i - nab] = 0;
    }
}

__global__ void hist_k(const int* __restrict__ eidx, const int* __restrict__ iedge,
                       int* __restrict__ kg_cnt, int* __restrict__ iu_cnt,
                       int* __restrict__ ii_cnt) {
    int stride = gridDim.x * blockDim.x;
    for (int i = blockIdx.x * blockDim.x + threadIdx.x; i < E_KG; i += stride)
        atomicAdd(&kg_cnt[eidx[i]], 1);
    for (int i = blockIdx.x * blockDim.x + threadIdx.x; i < E_IN; i += stride) {
        atomicAdd(&iu_cnt[iedge[i]], 1);
        atomicAdd(&ii_cnt[iedge[E_IN + i]], 1);
    }
}

// Three one-block exclusive scans in one launch (block 0: kg, 1: iu, 2: ii).
// cnt aliases cur (each element read by the owning thread before overwrite).
__global__ void __launch_bounds__(1024) scan3_k(int* __restrict__ kg_cur,
                                                int* __restrict__ kg_row,
                                                int* __restrict__ iu_cur,
                                                int* __restrict__ iu_row,
                                                int* __restrict__ ii_cur,
                                                int* __restrict__ ii_row) {
    const int* cnt; int* row; int* cur; int n;
    if (blockIdx.x == 0)      { cnt = kg_cur; row = kg_row; cur = kg_cur; n = N_ENT; }
    else if (blockIdx.x == 1) { cnt = iu_cur; row = iu_row; cur = iu_cur; n = N_USERS; }
    else                      { cnt = ii_cur; row = ii_row; cur = ii_cur; n = N_ENT; }

    __shared__ int wsum[32];
    __shared__ int base_s;
    int tid = threadIdx.x;
    int lane = tid & 31, w = tid >> 5;
    if (tid == 0) base_s = 0;
    __syncthreads();
    for (int b = 0; b < n; b += 4096) {
        int i = b + tid * 4;
        int4 v = (i + 3 < n) ? *(const int4*)&cnt[i] : make_int4(0, 0, 0, 0);
        int tsum = v.x + v.y + v.z + v.w;
        int x = tsum;
        #pragma unroll
        for (int o = 1; o < 32; o <<= 1) {
            int y = __shfl_up_sync(0xffffffffu, x, o);
            if (lane >= o) x += y;
        }
        if (lane == 31) wsum[w] = x;
        __syncthreads();
        if (w == 0) {
            int s = wsum[lane];
            #pragma unroll
            for (int o = 1; o < 32; o <<= 1) {
                int y = __shfl_up_sync(0xffffffffu, s, o);
                if (lane >= o) s += y;
            }
            wsum[lane] = s;
        }
        __syncthreads();
        int excl = x - tsum + (w ? wsum[w - 1] : 0) + base_s;
        if (i + 3 < n) {
            int4 o4 = make_int4(excl, excl + v.x, excl + v.x + v.y,
                                excl + v.x + v.y + v.z);
            *(int4*)&row[i] = o4;
            *(int4*)&cur[i] = o4;
        }
        __syncthreads();
        if (tid == 1023) base_s = excl + tsum;
        __syncthreads();
    }
    if (tid == 0) row[n] = base_s;
}

__global__ void scatter_k(const int* __restrict__ eidx, const int* __restrict__ etype,
                          const int* __restrict__ iedge, const float* __restrict__ iw,
                          int* __restrict__ kg_cur, unsigned* __restrict__ kg_pk,
                          int* __restrict__ iu_cur, int2* __restrict__ iu_pk,
                          int* __restrict__ ii_cur, int2* __restrict__ ii_pk) {
    int stride = gridDim.x * blockDim.x;
    for (int i = blockIdx.x * blockDim.x + threadIdx.x; i < E_KG; i += stride) {
        int hd = eidx[i];
        unsigned tl = (unsigned)eidx[E_KG + i];
        unsigned rt = (unsigned)(etype[i] - 1);
        int pos = atomicAdd(&kg_cur[hd], 1);
        kg_pk[pos] = tl | (rt << 20);
    }
    for (int i = blockIdx.x * blockDim.x + threadIdx.x; i < E_IN; i += stride) {
        int u = iedge[i];
        int it = iedge[E_IN + i];
        int wb = __float_as_int(iw[i]);
        int p1 = atomicAdd(&iu_cur[u], 1);
        iu_pk[p1] = make_int2(it, wb);
        int p2 = atomicAdd(&ii_cur[it], 1);
        ii_pk[p2] = make_int2(u, wb);
    }
}

// ---------------- per-layer kernels ----------------
// P[r,:] = X[r,:] @ W (64x64), output bf16. 256 threads = 16 rows x 16 col-quads.
__global__ void __launch_bounds__(256) gemm_k(const float* __restrict__ X,
                                              const float* __restrict__ W,
                                              __nv_bfloat162* __restrict__ P) {
    __shared__ float sW[64 * 64];
    __shared__ float srow[16][64];
    int tid = threadIdx.x;
    #pragma unroll
    for (int i = 0; i < 16; i++) sW[tid + i * 256] = W[tid + i * 256];
    const float4* X4 = (const float4*)(X + (size_t)blockIdx.x * 16 * 64);
    ((float4*)&srow[0][0])[tid] = X4[tid];
    __syncthreads();
    int r  = tid >> 4;
    int cq = (tid & 15) * 4;
    float4 acc = make_float4(0.f, 0.f, 0.f, 0.f);
    #pragma unroll
    for (int d = 0; d < 64; d++) {
        float a = srow[r][d];
        float4 b = *(const float4*)&sW[d * 64 + cq];
        acc.x += a * b.x; acc.y += a * b.y; acc.z += a * b.z; acc.w += a * b.w;
    }
    size_t o = ((size_t)blockIdx.x * 16 + r) * 32 + (cq >> 1);
    P[o]     = __float22bfloat162_rn(make_float2(acc.x, acc.y));
    P[o + 1] = __float22bfloat162_rn(make_float2(acc.z, acc.w));
}

// Fused node update: blocks [0, NB_ENT) do entities, [NB_ENT, NB_ENT+NB_USR) users.
// One warp per row; lane l owns dims 2l, 2l+1.
// FINAL=0: write new embedding to ent_out/usr_out.
// FINAL=1: write (orig + prev + new)/3 (the mean epilogue) instead.
template <int FINAL>
__global__ void __launch_bounds__(256) node_k(const int* __restrict__ kg_row,
                                              const unsigned* __restrict__ kg_pk,
                                              const int* __restrict__ ii_row,
                                              const int2* __restrict__ ii_pk,
                                              const int* __restrict__ iu_row,
                                              const int2* __restrict__ iu_pk,
                                              const __nv_bfloat162* __restrict__ P,
                                              const float* __restrict__ ent_cur,
                                              const float* __restrict__ usr_cur,
                                              const float* __restrict__ relemb,
                                              const float* __restrict__ ent_p0,
                                              const float* __restrict__ usr_p0,
                                              float* __restrict__ ent_out,
                                              float* __restrict__ usr_out) {
    int tid  = threadIdx.x;
    int lane = tid & 31;
    int d0   = lane * 2;
    const float c3 = 1.0f / 3.0f;

    if (blockIdx.x < NB_ENT) {
        // ---------------- entity path ----------------
        __shared__ float srel[N_REL * DIMS];
        #pragma unroll
        for (int i = 0; i < 4; i++) srel[tid + i * 256] = relemb[tid + i * 256];
        __syncthreads();

        int row = blockIdx.x * 8 + (tid >> 5);
        float2 ph = __bfloat1622float2(P[(size_t)row * 32 + lane]);

        float2 acc = make_float2(0.f, 0.f);
        float ssum = 0.f;
        int s = kg_row[row], e = kg_row[row + 1];
        int j = s;
        for (; j + 1 < e; j += 2) {
            unsigned pk0 = kg_pk[j], pk1 = kg_pk[j + 1];
            int tl0 = (int)(pk0 & 0xFFFFFu), rt0 = (int)(pk0 >> 20);
            int tl1 = (int)(pk1 & 0xFFFFFu), rt1 = (int)(pk1 >> 20);
            float2 pt0 = __bfloat1622float2(P[(size_t)tl0 * 32 + lane]);
            float2 pt1 = __bfloat1622float2(P[(size_t)tl1 * 32 + lane]);
            float2 rv0 = *(const float2*)&srel[rt0 * 64 + d0];
            float2 rv1 = *(const float2*)&srel[rt1 * 64 + d0];
            float2 te0 = *(const float2*)&ent_cur[(size_t)tl0 * 64 + d0];
            float2 te1 = *(const float2*)&ent_cur[(size_t)tl1 * 64 + d0];
            float p0 = ph.x * pt0.x * rv0.x + ph.y * pt0.y * rv0.y;
            float p1 = ph.x * pt1.x * rv1.x + ph.y * pt1.y * rv1.y;
            float r0 = half_reduce(p0);
            float r1 = half_reduce(p1);
            float ex0 = __expf(r0 * RSQRT_DK);
            float ex1 = __expf(r1 * RSQRT_DK);
            ssum += ex0 + ex1;
            acc.x += ex0 * te0.x * rv0.x + ex1 * te1.x * rv1.x;
            acc.y += ex0 * te0.y * rv0.y + ex1 * te1.y * rv1.y;
        }
        if (j < e) {
            unsigned pk0 = kg_pk[j];
            int tl0 = (int)(pk0 & 0xFFFFFu), rt0 = (int)(pk0 >> 20);
            float2 pt0 = __bfloat1622float2(P[(size_t)tl0 * 32 + lane]);
            float2 rv0 = *(const float2*)&srel[rt0 * 64 + d0];
            float2 te0 = *(const float2*)&ent_cur[(size_t)tl0 * 64 + d0];
            float p0 = ph.x * pt0.x * rv0.x + ph.y * pt0.y * rv0.y;
            float r0 = half_reduce(p0);
            float ex0 = __expf(r0 * RSQRT_DK);
            ssum += ex0;
            acc.x += ex0 * te0.x * rv0.x;
            acc.y += ex0 * te0.y * rv0.y;
        }
        float invs = (ssum > 0.f) ? (1.f / ssum) : 1.f;
        acc.x *= invs; acc.y *= invs;

        // L2 normalize over all 64 dims
        float s2 = acc.x * acc.x + acc.y * acc.y;
        s2 = half_reduce(s2);
        s2 += __shfl_xor_sync(0xffffffffu, s2, 16);
        float invn = 1.0f / fmaxf(sqrtf(s2), 1e-12f);
        acc.x *= invn; acc.y *= invn;

        // user -> entity aggregation
        int si = ii_row[row], ei = ii_row[row + 1];
        #pragma unroll 2
        for (int k = si; k < ei; k++) {
            int2 p = ii_pk[k];
            float w = __int_as_float(p.y);
            float2 uv = *(const float2*)&usr_cur[(size_t)p.x * 64 + d0];
            acc.x += w * uv.x;
            acc.y += w * uv.y;
        }
        if (FINAL) {
            // ent_cur here is the layer-1 output; ent_p0 is the original input.
            float2 a0 = *(const float2*)&ent_cur[(size_t)row * 64 + d0];
            float2 a1 = *(const float2*)&ent_p0[(size_t)row * 64 + d0];
            acc.x = (a0.x + a1.x + acc.x) * c3;
            acc.y = (a0.y + a1.y + acc.y) * c3;
        }
        *(float2*)&ent_out[(size_t)row * 64 + d0] = acc;
    } else {
        // ---------------- user path ----------------
        int row = (blockIdx.x - NB_ENT) * 8 + (tid >> 5);
        float2 acc = make_float2(0.f, 0.f);
        int s = iu_row[row], e = iu_row[row + 1];
        #pragma unroll 2
        for (int k = s; k < e; k++) {
            int2 p = iu_pk[k];
            float w = __int_as_float(p.y);
            float2 ev = *(const float2*)&ent_cur[(size_t)p.x * 64 + d0];
            acc.x += w * ev.x;
            acc.y += w * ev.y;
        }
        if (FINAL) {
            float2 a0 = *(const float2*)&usr_cur[(size_t)row * 64 + d0];  // layer-1 user
            float2 a1 = *(const float2*)&usr_p0[(size_t)row * 64 + d0];   // original input
            acc.x = (a0.x + a1.x + acc.x) * c3;
            acc.y = (a0.y + a1.y + acc.y) * c3;
        }
        *(float2*)&usr_out[(size_t)row * 64 + d0] = acc;
    }
}

// ---------------- launcher ----------------
extern "C" void kernel_launch(void* const* d_in, const int* in_sizes, int n_in,
                              void* d_out, int out_size) {
    const float* user_emb   = (const float*)d_in[1];
    const float* entity_emb = (const float*)d_in[2];
    const int*   inter_edge = (const int*)d_in[3];
    const float* inter_w    = (const float*)d_in[4];
    const int*   edge_index = (const int*)d_in[5];
    const int*   edge_type  = (const int*)d_in[6];
    const float* rel_emb    = (const float*)d_in[7];
    const float* W_Q        = (const float*)d_in[8];
    float* out = (float*)d_out;
    float* out_usr = out;
    float* out_ent = out + (size_t)N_USERS * DIMS;

    __nv_bfloat162* p_P;
    float *p_ent0, *p_usr0;
    int *p_kg_row, *p_kg_cur, *p_iu_row, *p_iu_cur, *p_ii_row, *p_ii_cur;
    unsigned* p_kg_pk;
    int2 *p_iu_pk, *p_ii_pk;
    cudaGetSymbolAddress((void**)&p_P,      g_P);
    cudaGetSymbolAddress((void**)&p_ent0,   g_ent0);
    cudaGetSymbolAddress((void**)&p_usr0,   g_usr0);
    cudaGetSymbolAddress((void**)&p_kg_row, g_kg_row);
    cudaGetSymbolAddress((void**)&p_kg_cur, g_kg_cur);
    cudaGetSymbolAddress((void**)&p_kg_pk,  g_kg_pk);
    cudaGetSymbolAddress((void**)&p_iu_row, g_iu_row);
    cudaGetSymbolAddress((void**)&p_iu_cur, g_iu_cur);
    cudaGetSymbolAddress((void**)&p_iu_pk,  g_iu_pk);
    cudaGetSymbolAddress((void**)&p_ii_row, g_ii_row);
    cudaGetSymbolAddress((void**)&p_ii_cur, g_ii_cur);
    cudaGetSymbolAddress((void**)&p_ii_pk,  g_ii_pk);

    const int TB = 256;
    const int NB_NODE = NB_ENT + NB_USR;   // 18750

    // ---- CSR build (shared by both layers) ----
    zero_cnt_k<<<512, TB>>>(p_kg_cur, N_ENT, p_iu_cur, N_USERS, p_ii_cur, N_ENT);
    hist_k<<<4096, TB>>>(edge_index, inter_edge, p_kg_cur, p_iu_cur, p_ii_cur);
    scan3_k<<<3, 1024>>>(p_kg_cur, p_kg_row, p_iu_cur, p_iu_row, p_ii_cur, p_ii_row);
    scatter_k<<<4096, TB>>>(edge_index, edge_type, inter_edge, inter_w,
                            p_kg_cur, p_kg_pk, p_iu_cur, p_iu_pk, p_ii_cur, p_ii_pk);

    // ---- layer 1 ----
    gemm_k<<<N_ENT / 16, TB>>>(entity_emb, W_Q, p_P);
    node_k<0><<<NB_NODE, TB>>>(p_kg_row, p_kg_pk, p_ii_row, p_ii_pk, p_iu_row, p_iu_pk,
                               p_P, entity_emb, user_emb, rel_emb,
                               nullptr, nullptr, p_ent0, p_usr0);

    // ---- layer 2 (writes the 3-layer mean directly to out) ----
    gemm_k<<<N_ENT / 16, TB>>>(p_ent0, W_Q, p_P);
    node_k<1><<<NB_NODE, TB>>>(p_kg_row, p_kg_pk, p_ii_row, p_ii_pk, p_iu_row, p_iu_pk,
                               p_P, p_ent0, p_usr0, rel_emb,
                               entity_emb, user_emb, out_ent, out_usr);
}